// round 1
// baseline (speedup 1.0000x reference)
#include <cuda_runtime.h>
#include <cuda_bf16.h>
#include <cstdint>
#include <cstddef>

#define TOKENS 32768
#define DIM    1024
#define HMID   512
#define HLOW   256

// ---------------- static device scratch (no allocations allowed) ----------------
__device__ uint32_t g_h0[(size_t)TOKENS * DIM];   // packed hi/lo bf16 of LN(x)
__device__ uint32_t g_h1[(size_t)TOKENS * HMID];
__device__ uint32_t g_h2[(size_t)TOKENS * HMID];
__device__ uint32_t g_h3[(size_t)TOKENS * HLOW];
__device__ uint32_t g_W1p[DIM  * HMID];           // transposed packed weights [M][K]
__device__ uint32_t g_W2p[HMID * HMID];
__device__ uint32_t g_W3p[HMID * HLOW];
__device__ uint32_t g_W4p[HLOW * DIM];

// ---------------- helpers ----------------
__device__ __forceinline__ uint32_t pack_hilo(float v) {
    __nv_bfloat16 h = __float2bfloat16_rn(v);
    float hf = __bfloat162float(h);
    __nv_bfloat16 l = __float2bfloat16_rn(v - hf);
    return (uint32_t)__bfloat16_as_ushort(h) | ((uint32_t)__bfloat16_as_ushort(l) << 16);
}

__device__ __forceinline__ float gelu_exact(float v) {
    return 0.5f * v * (1.0f + erff(v * 0.70710678118654752440f));
}

__device__ __forceinline__ void mma16816(float c[4], const uint32_t a[4], const uint32_t b[2]) {
    asm volatile(
        "mma.sync.aligned.m16n8k16.row.col.f32.bf16.bf16.f32 "
        "{%0,%1,%2,%3}, {%4,%5,%6,%7}, {%8,%9}, {%0,%1,%2,%3};\n"
        : "+f"(c[0]), "+f"(c[1]), "+f"(c[2]), "+f"(c[3])
        : "r"(a[0]), "r"(a[1]), "r"(a[2]), "r"(a[3]), "r"(b[0]), "r"(b[1]));
}

// ---------------- weight repack: W[K][M] fp32 -> Wt[M][K] packed hi/lo ----------------
__global__ void convw_kernel(const float* __restrict__ W, int K, int M, int which) {
    uint32_t* Wt = (which == 0) ? g_W1p : (which == 1) ? g_W2p : (which == 2) ? g_W3p : g_W4p;
    int idx = blockIdx.x * blockDim.x + threadIdx.x;
    if (idx >= K * M) return;
    int k = idx / M;
    int m = idx - k * M;
    Wt[(size_t)m * K + k] = pack_hilo(W[idx]);
}

// ---------------- LayerNorm: fp32 in -> packed hi/lo out ----------------
__global__ void ln_kernel(const float* __restrict__ x, const float* __restrict__ gamma,
                          const float* __restrict__ beta) {
    int row = blockIdx.x;
    int tid = threadIdx.x;                 // 256 threads, 4 elems each
    const float4* xr = (const float4*)(x + (size_t)row * DIM);
    float4 v = xr[tid];
    float s  = v.x + v.y + v.z + v.w;
    float sq = v.x * v.x + v.y * v.y + v.z * v.z + v.w * v.w;
    #pragma unroll
    for (int o = 16; o > 0; o >>= 1) {
        s  += __shfl_xor_sync(0xFFFFFFFFu, s,  o);
        sq += __shfl_xor_sync(0xFFFFFFFFu, sq, o);
    }
    __shared__ float ss[8], ssq[8];
    if ((tid & 31) == 0) { ss[tid >> 5] = s; ssq[tid >> 5] = sq; }
    __syncthreads();
    float S = 0.f, SQ = 0.f;
    #pragma unroll
    for (int i = 0; i < 8; i++) { S += ss[i]; SQ += ssq[i]; }
    float mu   = S * (1.0f / DIM);
    float var  = SQ * (1.0f / DIM) - mu * mu;
    float rstd = rsqrtf(var + 1e-5f);
    float4 gm = ((const float4*)gamma)[tid];
    float4 bt = ((const float4*)beta)[tid];
    uint4 o;
    o.x = pack_hilo((v.x - mu) * rstd * gm.x + bt.x);
    o.y = pack_hilo((v.y - mu) * rstd * gm.y + bt.y);
    o.z = pack_hilo((v.z - mu) * rstd * gm.z + bt.z);
    o.w = pack_hilo((v.w - mu) * rstd * gm.w + bt.w);
    ((uint4*)(g_h0 + (size_t)row * DIM))[tid] = o;
}

// ---------------- fused GEMM: C[N x M] = act(A[N x K] @ W[K x M] + b) ----------------
// A packed hi/lo u32 per element; Wt transposed packed [M][K].
// EPI==0: GELU + repack for next layer.  EPI==1: residual + bias, fp32 out.
template<int K, int M, int EPI>
__device__ __forceinline__ void gemm_body(
    const uint32_t* __restrict__ A, const uint32_t* __restrict__ Wt,
    const float* __restrict__ bias, uint32_t* __restrict__ outp,
    const float* __restrict__ xres, float* __restrict__ fout)
{
    constexpr int AS = 36;   // padded u32 stride
    __shared__ uint32_t A_sm[128][AS];
    __shared__ uint32_t W_sm[64][AS];

    const int tid  = threadIdx.x;
    const int lane = tid & 31;
    const int warp = tid >> 5;
    const int wm = warp >> 1;       // 0..3 (rows)
    const int wn = warp & 1;        // 0..1 (cols)
    const int g  = lane >> 2;       // 0..7
    const int t  = lane & 3;        // 0..3
    const int bm = blockIdx.y;
    const int bn = blockIdx.x;

    float acc[2][4][4];
    #pragma unroll
    for (int mi = 0; mi < 2; mi++)
        #pragma unroll
        for (int ni = 0; ni < 4; ni++)
            #pragma unroll
            for (int r = 0; r < 4; r++) acc[mi][ni][r] = 0.f;

    const uint32_t* gA = A  + (size_t)bm * 128 * K;
    const uint32_t* gW = Wt + (size_t)bn * 64  * K;
    const int lr = tid >> 3;           // 0..31
    const int lc = (tid & 7) << 2;     // 0,4,...,28

    for (int k0 = 0; k0 < K; k0 += 32) {
        #pragma unroll
        for (int i = 0; i < 4; i++) {
            int r = lr + i * 32;
            uint4 v = *(const uint4*)(gA + (size_t)r * K + k0 + lc);
            *(uint4*)&A_sm[r][lc] = v;
        }
        #pragma unroll
        for (int i = 0; i < 2; i++) {
            int r = lr + i * 32;
            uint4 v = *(const uint4*)(gW + (size_t)r * K + k0 + lc);
            *(uint4*)&W_sm[r][lc] = v;
        }
        __syncthreads();

        #pragma unroll
        for (int ks = 0; ks < 2; ks++) {
            const int kb = ks * 16;
            uint32_t ahi[2][4], alo[2][4];
            #pragma unroll
            for (int mi = 0; mi < 2; mi++) {
                int r = wm * 32 + mi * 16 + g;
                uint2 p0 = *(const uint2*)&A_sm[r    ][kb + 2 * t    ];
                uint2 p1 = *(const uint2*)&A_sm[r + 8][kb + 2 * t    ];
                uint2 p2 = *(const uint2*)&A_sm[r    ][kb + 2 * t + 8];
                uint2 p3 = *(const uint2*)&A_sm[r + 8][kb + 2 * t + 8];
                ahi[mi][0] = __byte_perm(p0.x, p0.y, 0x5410);
                alo[mi][0] = __byte_perm(p0.x, p0.y, 0x7632);
                ahi[mi][1] = __byte_perm(p1.x, p1.y, 0x5410);
                alo[mi][1] = __byte_perm(p1.x, p1.y, 0x7632);
                ahi[mi][2] = __byte_perm(p2.x, p2.y, 0x5410);
                alo[mi][2] = __byte_perm(p2.x, p2.y, 0x7632);
                ahi[mi][3] = __byte_perm(p3.x, p3.y, 0x5410);
                alo[mi][3] = __byte_perm(p3.x, p3.y, 0x7632);
            }
            uint32_t bhi[4][2], blo[4][2];
            #pragma unroll
            for (int ni = 0; ni < 4; ni++) {
                int r = wn * 32 + ni * 8 + g;
                uint2 q0 = *(const uint2*)&W_sm[r][kb + 2 * t    ];
                uint2 q1 = *(const uint2*)&W_sm[r][kb + 2 * t + 8];
                bhi[ni][0] = __byte_perm(q0.x, q0.y, 0x5410);
                blo[ni][0] = __byte_perm(q0.x, q0.y, 0x7632);
                bhi[ni][1] = __byte_perm(q1.x, q1.y, 0x5410);
                blo[ni][1] = __byte_perm(q1.x, q1.y, 0x7632);
            }
            #pragma unroll
            for (int mi = 0; mi < 2; mi++)
                #pragma unroll
                for (int ni = 0; ni < 4; ni++) {
                    mma16816(acc[mi][ni], ahi[mi], bhi[ni]);  // hi*hi
                    mma16816(acc[mi][ni], ahi[mi], blo[ni]);  // hi*lo
                    mma16816(acc[mi][ni], alo[mi], bhi[ni]);  // lo*hi
                }
        }
        __syncthreads();
    }

    // ---------------- epilogue ----------------
    #pragma unroll
    for (int mi = 0; mi < 2; mi++) {
        #pragma unroll
        for (int ni = 0; ni < 4; ni++) {
            int r = bm * 128 + wm * 32 + mi * 16 + g;
            int c = bn * 64 + wn * 32 + ni * 8 + 2 * t;
            float2 bb = *(const float2*)&bias[c];
            if (EPI == 0) {
                uint2 o0, o1;
                o0.x = pack_hilo(gelu_exact(acc[mi][ni][0] + bb.x));
                o0.y = pack_hilo(gelu_exact(acc[mi][ni][1] + bb.y));
                o1.x = pack_hilo(gelu_exact(acc[mi][ni][2] + bb.x));
                o1.y = pack_hilo(gelu_exact(acc[mi][ni][3] + bb.y));
                *(uint2*)&outp[(size_t)r * M + c]       = o0;
                *(uint2*)&outp[(size_t)(r + 8) * M + c] = o1;
            } else {
                float2 x0 = *(const float2*)&xres[(size_t)r * M + c];
                float2 x1 = *(const float2*)&xres[(size_t)(r + 8) * M + c];
                float2 o0 = make_float2(x0.x + acc[mi][ni][0] + bb.x,
                                        x0.y + acc[mi][ni][1] + bb.y);
                float2 o1 = make_float2(x1.x + acc[mi][ni][2] + bb.x,
                                        x1.y + acc[mi][ni][3] + bb.y);
                *(float2*)&fout[(size_t)r * M + c]       = o0;
                *(float2*)&fout[(size_t)(r + 8) * M + c] = o1;
            }
        }
    }
}

__global__ void __launch_bounds__(256) gemm1_kernel(const float* __restrict__ bias) {
    gemm_body<DIM, HMID, 0>(g_h0, g_W1p, bias, g_h1, nullptr, nullptr);
}
__global__ void __launch_bounds__(256) gemm2_kernel(const float* __restrict__ bias) {
    gemm_body<HMID, HMID, 0>(g_h1, g_W2p, bias, g_h2, nullptr, nullptr);
}
__global__ void __launch_bounds__(256) gemm3_kernel(const float* __restrict__ bias) {
    gemm_body<HMID, HLOW, 0>(g_h2, g_W3p, bias, g_h3, nullptr, nullptr);
}
__global__ void __launch_bounds__(256) gemm4_kernel(const float* __restrict__ bias,
                                                    const float* __restrict__ xres,
                                                    float* __restrict__ fout) {
    gemm_body<HLOW, DIM, 1>(g_h3, g_W4p, bias, nullptr, xres, fout);
}

// ---------------- launch ----------------
extern "C" void kernel_launch(void* const* d_in, const int* in_sizes, int n_in,
                              void* d_out, int out_size) {
    const float* x     = (const float*)d_in[0];
    const float* gamma = (const float*)d_in[1];
    const float* beta  = (const float*)d_in[2];
    const float* W1    = (const float*)d_in[3];
    const float* b1    = (const float*)d_in[4];
    const float* W2    = (const float*)d_in[5];
    const float* b2    = (const float*)d_in[6];
    const float* W3    = (const float*)d_in[7];
    const float* b3    = (const float*)d_in[8];
    const float* W4    = (const float*)d_in[9];
    const float* b4    = (const float*)d_in[10];
    float* out = (float*)d_out;

    convw_kernel<<<(DIM  * HMID + 255) / 256, 256>>>(W1, DIM,  HMID, 0);
    convw_kernel<<<(HMID * HMID + 255) / 256, 256>>>(W2, HMID, HMID, 1);
    convw_kernel<<<(HMID * HLOW + 255) / 256, 256>>>(W3, HMID, HLOW, 2);
    convw_kernel<<<(HLOW * DIM  + 255) / 256, 256>>>(W4, HLOW, DIM,  3);

    ln_kernel<<<TOKENS, 256>>>(x, gamma, beta);

    gemm1_kernel<<<dim3(HMID / 64, TOKENS / 128), 256>>>(b1);
    gemm2_kernel<<<dim3(HMID / 64, TOKENS / 128), 256>>>(b2);
    gemm3_kernel<<<dim3(HLOW / 64, TOKENS / 128), 256>>>(b3);
    gemm4_kernel<<<dim3(DIM  / 64, TOKENS / 128), 256>>>(b4, x, out);
}

// round 4
// speedup vs baseline: 2.8801x; 2.8801x over previous
#include <cuda_runtime.h>
#include <cuda_fp16.h>
#include <cstdint>
#include <cstddef>

#define TOKENS 32768
#define DIM    1024
#define HMID   512
#define HLOW   256

// ---------------- static device scratch (fp16x2 packed in u32) ----------------
__device__ uint32_t g_h0[(size_t)TOKENS * DIM  / 2];
__device__ uint32_t g_h1[(size_t)TOKENS * HMID / 2];
__device__ uint32_t g_h2[(size_t)TOKENS * HMID / 2];
__device__ uint32_t g_h3[(size_t)TOKENS * HLOW / 2];
__device__ uint32_t g_W1p[HMID * DIM  / 2];   // [M][K/2] transposed packed
__device__ uint32_t g_W2p[HMID * HMID / 2];
__device__ uint32_t g_W3p[HLOW * HMID / 2];
__device__ uint32_t g_W4p[DIM  * HLOW / 2];

// ---------------- helpers ----------------
__device__ __forceinline__ uint32_t pack2(float a, float b) {
    __half2 h = __floats2half2_rn(a, b);
    return *(uint32_t*)&h;
}
__device__ __forceinline__ float gelu_exact(float v) {
    return 0.5f * v * (1.0f + erff(v * 0.70710678118654752440f));
}
__device__ __forceinline__ void mma16816(float c[4], const uint32_t a[4], const uint32_t b[2]) {
    asm volatile(
        "mma.sync.aligned.m16n8k16.row.col.f32.f16.f16.f32 "
        "{%0,%1,%2,%3}, {%4,%5,%6,%7}, {%8,%9}, {%0,%1,%2,%3};\n"
        : "+f"(c[0]), "+f"(c[1]), "+f"(c[2]), "+f"(c[3])
        : "r"(a[0]), "r"(a[1]), "r"(a[2]), "r"(a[3]), "r"(b[0]), "r"(b[1]));
}
__device__ __forceinline__ void ldsm_x4(uint32_t& r0, uint32_t& r1, uint32_t& r2, uint32_t& r3,
                                        uint32_t addr) {
    asm volatile("ldmatrix.sync.aligned.m8n8.x4.shared.b16 {%0,%1,%2,%3}, [%4];\n"
                 : "=r"(r0), "=r"(r1), "=r"(r2), "=r"(r3) : "r"(addr));
}
__device__ __forceinline__ void cp_async16(uint32_t dst, const void* src) {
    asm volatile("cp.async.cg.shared.global [%0], [%1], 16;\n" :: "r"(dst), "l"(src));
}
__device__ __forceinline__ void cp_commit() { asm volatile("cp.async.commit_group;\n"); }
__device__ __forceinline__ void cp_wait0()  { asm volatile("cp.async.wait_group 0;\n" ::: "memory"); }

// ---------------- merged weight repack: W[K][M] fp32 -> Wt[M][K/2] fp16x2 ----------------
__device__ __forceinline__ void repack_one(const float* __restrict__ W, uint32_t* __restrict__ Wt,
                                           int M, int KU, int idx) {
    int kp = idx / M;
    int m  = idx - kp * M;
    float w0 = W[(size_t)(2 * kp)     * M + m];   // coalesced over m
    float w1 = W[(size_t)(2 * kp + 1) * M + m];
    Wt[(size_t)m * KU + kp] = pack2(w0, w1);
}
#define R1 (512 * 512)
#define R2 (R1 + 512 * 256)
#define R3 (R2 + 256 * 256)
#define R4 (R3 + 1024 * 128)
__global__ void convw_all_kernel(const float* __restrict__ W1, const float* __restrict__ W2,
                                 const float* __restrict__ W3, const float* __restrict__ W4) {
    int idx = blockIdx.x * blockDim.x + threadIdx.x;
    if (idx < R1)       repack_one(W1, g_W1p, HMID, DIM  / 2, idx);
    else if (idx < R2)  repack_one(W2, g_W2p, HMID, HMID / 2, idx - R1);
    else if (idx < R3)  repack_one(W3, g_W3p, HLOW, HMID / 2, idx - R2);
    else if (idx < R4)  repack_one(W4, g_W4p, DIM,  HLOW / 2, idx - R3);
}

// ---------------- LayerNorm: fp32 in -> fp16x2 out ----------------
__global__ void ln_kernel(const float* __restrict__ x, const float* __restrict__ gamma,
                          const float* __restrict__ beta) {
    int row = blockIdx.x;
    int tid = threadIdx.x;                 // 256 threads, 4 elems each
    const float4* xr = (const float4*)(x + (size_t)row * DIM);
    float4 v = xr[tid];
    float s  = v.x + v.y + v.z + v.w;
    float sq = v.x * v.x + v.y * v.y + v.z * v.z + v.w * v.w;
    #pragma unroll
    for (int o = 16; o > 0; o >>= 1) {
        s  += __shfl_xor_sync(0xFFFFFFFFu, s,  o);
        sq += __shfl_xor_sync(0xFFFFFFFFu, sq, o);
    }
    __shared__ float ss[8], ssq[8];
    if ((tid & 31) == 0) { ss[tid >> 5] = s; ssq[tid >> 5] = sq; }
    __syncthreads();
    float S = 0.f, SQ = 0.f;
    #pragma unroll
    for (int i = 0; i < 8; i++) { S += ss[i]; SQ += ssq[i]; }
    float mu   = S * (1.0f / DIM);
    float var  = SQ * (1.0f / DIM) - mu * mu;
    float rstd = rsqrtf(var + 1e-5f);
    float4 gm = ((const float4*)gamma)[tid];
    float4 bt = ((const float4*)beta)[tid];
    uint2 o;
    o.x = pack2((v.x - mu) * rstd * gm.x + bt.x, (v.y - mu) * rstd * gm.y + bt.y);
    o.y = pack2((v.z - mu) * rstd * gm.z + bt.z, (v.w - mu) * rstd * gm.w + bt.w);
    ((uint2*)(g_h0 + (size_t)row * (DIM / 2)))[tid] = o;
}

// ---------------- fused GEMM: C[N x M] = act(A[N x K] @ W[K x M] + b) ----------------
// A: [rows][K/2] fp16x2.  Wt: [M][K/2] fp16x2.  128x64 block tile, 8 warps, 2-stage cp.async.
// Smem: XOR-swizzled, row stride 32 u32 (128B). K-tile = 64 fp16 = 32 u32.
template<int K, int M, int EPI>
__device__ __forceinline__ void gemm_body(
    const uint32_t* __restrict__ A, const uint32_t* __restrict__ Wt,
    const float* __restrict__ bias, uint32_t* __restrict__ outp,
    const float* __restrict__ xres, float* __restrict__ fout)
{
    constexpr int KU = K / 2;
    constexpr int NT = K / 64;
    __shared__ uint32_t sm[2 * (128 + 64) * 32];    // 48 KB
    uint32_t* A_sm = sm;                            // [2][128][32]
    uint32_t* W_sm = sm + 2 * 128 * 32;             // [2][64][32]

    const int tid  = threadIdx.x;
    const int lane = tid & 31;
    const int warp = tid >> 5;
    const int wm = warp >> 1;       // 0..3
    const int wn = warp & 1;        // 0..1
    const int bm = blockIdx.y;
    const int bn = blockIdx.x;

    const uint32_t* gA = A  + (size_t)bm * 128 * KU;
    const uint32_t* gW = Wt + (size_t)bn * 64  * KU;
    const int ldr = tid >> 3;          // 0..31
    const int ldc = tid & 7;           // 16B chunk 0..7

    const uint32_t aBase = (uint32_t)__cvta_generic_to_shared(A_sm);
    const uint32_t wBase = (uint32_t)__cvta_generic_to_shared(W_sm);

    float acc[2][4][4];
    #pragma unroll
    for (int mi = 0; mi < 2; mi++)
        #pragma unroll
        for (int ni = 0; ni < 4; ni++)
            #pragma unroll
            for (int r = 0; r < 4; r++) acc[mi][ni][r] = 0.f;

    auto prefetch = [&](int kt, int st) {
        const int k0 = kt * 32;
        #pragma unroll
        for (int i = 0; i < 4; i++) {
            int r = ldr + i * 32;
            uint32_t dst = aBase + (uint32_t)(st * 128 * 32 + r * 32 + ((ldc ^ (r & 7)) << 2)) * 4;
            cp_async16(dst, gA + (size_t)r * KU + k0 + ldc * 4);
        }
        #pragma unroll
        for (int i = 0; i < 2; i++) {
            int r = ldr + i * 32;
            uint32_t dst = wBase + (uint32_t)(st * 64 * 32 + r * 32 + ((ldc ^ (r & 7)) << 2)) * 4;
            cp_async16(dst, gW + (size_t)r * KU + k0 + ldc * 4);
        }
    };

    prefetch(0, 0);
    cp_commit();

    for (int kt = 0; kt < NT; kt++) {
        cp_wait0();
        __syncthreads();
        if (kt + 1 < NT) { prefetch(kt + 1, (kt + 1) & 1); cp_commit(); }
        const int st = kt & 1;
        const uint32_t aS = aBase + (uint32_t)(st * 128 * 32) * 4;
        const uint32_t wS = wBase + (uint32_t)(st * 64  * 32) * 4;

        #pragma unroll
        for (int ks = 0; ks < 4; ks++) {
            // A fragments via ldmatrix.x4 (one per 16-row slab)
            uint32_t af[2][4];
            #pragma unroll
            for (int mi = 0; mi < 2; mi++) {
                int row = wm * 32 + mi * 16 + (lane & 15);
                int ch  = (ks * 2 + (lane >> 4)) ^ (row & 7);
                uint32_t addr = aS + (uint32_t)(row * 32 + (ch << 2)) * 4;
                ldsm_x4(af[mi][0], af[mi][1], af[mi][2], af[mi][3], addr);
            }
            // B fragments via ldmatrix.x4 (two ni per load)
            uint32_t bf[4][2];
            #pragma unroll
            for (int np = 0; np < 2; np++) {
                int col = wn * 32 + np * 16 + ((lane >> 4) << 3) + (lane & 7);
                int ch  = (ks * 2 + ((lane >> 3) & 1)) ^ (col & 7);
                uint32_t addr = wS + (uint32_t)(col * 32 + (ch << 2)) * 4;
                ldsm_x4(bf[2 * np][0], bf[2 * np][1], bf[2 * np + 1][0], bf[2 * np + 1][1], addr);
            }
            #pragma unroll
            for (int mi = 0; mi < 2; mi++)
                #pragma unroll
                for (int ni = 0; ni < 4; ni++)
                    mma16816(acc[mi][ni], af[mi], bf[ni]);
        }
        __syncthreads();
    }

    // ---------------- epilogue ----------------
    const int g = lane >> 2;
    const int t = lane & 3;
    #pragma unroll
    for (int mi = 0; mi < 2; mi++) {
        #pragma unroll
        for (int ni = 0; ni < 4; ni++) {
            int r = bm * 128 + wm * 32 + mi * 16 + g;
            int c = bn * 64 + wn * 32 + ni * 8 + 2 * t;
            float2 bb = *(const float2*)&bias[c];
            if (EPI == 0) {
                outp[(size_t)r * (M / 2) + (c >> 1)] =
                    pack2(gelu_exact(acc[mi][ni][0] + bb.x), gelu_exact(acc[mi][ni][1] + bb.y));
                outp[(size_t)(r + 8) * (M / 2) + (c >> 1)] =
                    pack2(gelu_exact(acc[mi][ni][2] + bb.x), gelu_exact(acc[mi][ni][3] + bb.y));
            } else {
                float2 x0 = *(const float2*)&xres[(size_t)r * M + c];
                float2 x1 = *(const float2*)&xres[(size_t)(r + 8) * M + c];
                float2 o0 = make_float2(x0.x + acc[mi][ni][0] + bb.x,
                                        x0.y + acc[mi][ni][1] + bb.y);
                float2 o1 = make_float2(x1.x + acc[mi][ni][2] + bb.x,
                                        x1.y + acc[mi][ni][3] + bb.y);
                *(float2*)&fout[(size_t)r * M + c]       = o0;
                *(float2*)&fout[(size_t)(r + 8) * M + c] = o1;
            }
        }
    }
}

__global__ void __launch_bounds__(256) gemm1_kernel(const float* __restrict__ bias) {
    gemm_body<DIM, HMID, 0>(g_h0, g_W1p, bias, g_h1, nullptr, nullptr);
}
__global__ void __launch_bounds__(256) gemm2_kernel(const float* __restrict__ bias) {
    gemm_body<HMID, HMID, 0>(g_h1, g_W2p, bias, g_h2, nullptr, nullptr);
}
__global__ void __launch_bounds__(256) gemm3_kernel(const float* __restrict__ bias) {
    gemm_body<HMID, HLOW, 0>(g_h2, g_W3p, bias, g_h3, nullptr, nullptr);
}
__global__ void __launch_bounds__(256) gemm4_kernel(const float* __restrict__ bias,
                                                    const float* __restrict__ xres,
                                                    float* __restrict__ fout) {
    gemm_body<HLOW, DIM, 1>(g_h3, g_W4p, bias, nullptr, xres, fout);
}

// ---------------- launch ----------------
extern "C" void kernel_launch(void* const* d_in, const int* in_sizes, int n_in,
                              void* d_out, int out_size) {
    const float* x     = (const float*)d_in[0];
    const float* gamma = (const float*)d_in[1];
    const float* beta  = (const float*)d_in[2];
    const float* W1    = (const float*)d_in[3];
    const float* b1    = (const float*)d_in[4];
    const float* W2    = (const float*)d_in[5];
    const float* b2    = (const float*)d_in[6];
    const float* W3    = (const float*)d_in[7];
    const float* b3    = (const float*)d_in[8];
    const float* W4    = (const float*)d_in[9];
    const float* b4    = (const float*)d_in[10];
    float* out = (float*)d_out;

    convw_all_kernel<<<(R4 + 255) / 256, 256>>>(W1, W2, W3, W4);
    ln_kernel<<<TOKENS, 256>>>(x, gamma, beta);

    gemm1_kernel<<<dim3(HMID / 64, TOKENS / 128), 256>>>(b1);
    gemm2_kernel<<<dim3(HMID / 64, TOKENS / 128), 256>>>(b2);
    gemm3_kernel<<<dim3(HLOW / 64, TOKENS / 128), 256>>>(b3);
    gemm4_kernel<<<dim3(DIM  / 64, TOKENS / 128), 256>>>(b4, x, out);
}